// round 1
// baseline (speedup 1.0000x reference)
#include <cuda_runtime.h>
#include <math.h>

// Problem constants
#define BB 64
#define TT 256
#define FF 64
#define UU 512
#define GG 2048   // 4*UU

// Scratch (static device allocations — allowed; no cudaMalloc anywhere)
__device__ float g_hs[BB * TT * UU];   // all hidden states (33.5 MB)
__device__ float g_c[BB * UU];         // cell state
__device__ float g_coef[TT];
__device__ float g_shift[TT];
__device__ float g_sumW;

__device__ __forceinline__ float sigmoidf_(float x) { return 1.f / (1.f + expf(-x)); }

// ---------------------------------------------------------------------------
// Prep: coef[t] = (t==0)?1:sum_{j<t} att_W[t,j];  shift[t] = (t==0)?0:att_b[t];
// sumW = sum(out_W)
// ---------------------------------------------------------------------------
__global__ void prep_kernel(const float* __restrict__ attW,
                            const float* __restrict__ attb,
                            const float* __restrict__ outW)
{
    int t = threadIdx.x;   // 256 threads
    float s = 0.f;
    for (int j = 0; j < t; ++j) s += attW[t * TT + j];
    g_coef[t]  = (t == 0) ? 1.f : s;
    g_shift[t] = (t == 0) ? 0.f : attb[t];

    __shared__ float red[256];
    red[t] = outW[t] + outW[t + 256];
    __syncthreads();
    for (int off = 128; off > 0; off >>= 1) {
        if (t < off) red[t] += red[t + off];
        __syncthreads();
    }
    if (t == 0) g_sumW = red[0];
}

// ---------------------------------------------------------------------------
// One LSTM time step.
// Grid: 64 blocks = 16 batch-groups (4 batches) x 4 unit-chunks (128 units).
// Block: 128 threads.
// GEMM phase: thread = (gate = tid>>5, 4 consecutive units j4 = (tid&31)*4),
//             accumulates 4 batches x 4 cols, rec loaded as float4 (coalesced),
//             h_prev broadcast from smem. Input projection (K=64) folded in.
// Pointwise phase: via smem exchange, thread owns 1 unit x 4 batches and has
//             all 4 gates; updates c and writes h into g_hs[:, t, :].
// Step t reads g_hs[:, t-1, :] -> no cross-block hazard across launches.
// ---------------------------------------------------------------------------
__global__ void lstm_step_kernel(const float* __restrict__ x,     // (B,T,F)
                                 const float* __restrict__ Wk,    // (F,4U)
                                 const float* __restrict__ Rk,    // (U,4U)
                                 const float* __restrict__ bias,  // (4U)
                                 int t)
{
    __shared__ float sh[4 * UU];   // h_prev  [bb*512 + k]      (8 KB)
    __shared__ float sx[4 * FF];   // inputs  [bb*64 + f]       (1 KB)
    __shared__ float sg[4 * UU];   // gates   [bb*512 + gate*128 + lu]  (8 KB)

    const int tid = threadIdx.x;           // 0..127
    const int bg  = blockIdx.x >> 2;       // 0..15
    const int uc  = blockIdx.x & 3;        // 0..3
    const int b0  = bg * 4;
    const int u0  = uc * 128;

    // Stage h_prev (zeros at t==0 handled by skipping the rec loop)
    if (t > 0) {
        for (int idx = tid; idx < 4 * UU; idx += 128) {
            int bb = idx >> 9;
            int k  = idx & (UU - 1);
            sh[idx] = g_hs[((size_t)(b0 + bb) * TT + (t - 1)) * UU + k];
        }
    }
    // Stage this step's input rows
    for (int idx = tid; idx < 4 * FF; idx += 128) {
        int bb = idx >> 6;
        int f  = idx & (FF - 1);
        sx[idx] = x[((size_t)(b0 + bb) * TT + t) * FF + f];
    }
    __syncthreads();

    const int gate = tid >> 5;              // 0..3
    const int j4   = (tid & 31) << 2;       // 0,4,...,124
    const int col0 = gate * UU + u0 + j4;   // global gate-column

    float4 bv = *(const float4*)(bias + col0);
    float4 acc0 = bv, acc1 = bv, acc2 = bv, acc3 = bv;

    if (t > 0) {
        #pragma unroll 8
        for (int k = 0; k < UU; ++k) {
            float4 r = *(const float4*)(Rk + (size_t)k * GG + col0);
            float h0 = sh[0 * UU + k];
            float h1 = sh[1 * UU + k];
            float h2 = sh[2 * UU + k];
            float h3 = sh[3 * UU + k];
            acc0.x += h0 * r.x; acc0.y += h0 * r.y; acc0.z += h0 * r.z; acc0.w += h0 * r.w;
            acc1.x += h1 * r.x; acc1.y += h1 * r.y; acc1.z += h1 * r.z; acc1.w += h1 * r.w;
            acc2.x += h2 * r.x; acc2.y += h2 * r.y; acc2.z += h2 * r.z; acc2.w += h2 * r.w;
            acc3.x += h3 * r.x; acc3.y += h3 * r.y; acc3.z += h3 * r.z; acc3.w += h3 * r.w;
        }
    }
    // Input projection (K = 64)
    #pragma unroll 8
    for (int f = 0; f < FF; ++f) {
        float4 w = *(const float4*)(Wk + (size_t)f * GG + col0);
        float x0 = sx[0 * FF + f];
        float x1 = sx[1 * FF + f];
        float x2 = sx[2 * FF + f];
        float x3 = sx[3 * FF + f];
        acc0.x += x0 * w.x; acc0.y += x0 * w.y; acc0.z += x0 * w.z; acc0.w += x0 * w.w;
        acc1.x += x1 * w.x; acc1.y += x1 * w.y; acc1.z += x1 * w.z; acc1.w += x1 * w.w;
        acc2.x += x2 * w.x; acc2.y += x2 * w.y; acc2.z += x2 * w.z; acc2.w += x2 * w.w;
        acc3.x += x3 * w.x; acc3.y += x3 * w.y; acc3.z += x3 * w.z; acc3.w += x3 * w.w;
    }

    // Exchange gate values via smem (local layout: gate*128 + local_unit)
    const int lbase = gate * 128 + j4;
    *(float4*)(sg + 0 * UU + lbase) = acc0;
    *(float4*)(sg + 1 * UU + lbase) = acc1;
    *(float4*)(sg + 2 * UU + lbase) = acc2;
    *(float4*)(sg + 3 * UU + lbase) = acc3;
    __syncthreads();

    // Pointwise: thread owns unit lu = tid for 4 batches
    const int lu = tid;
    #pragma unroll
    for (int bb = 0; bb < 4; ++bb) {
        float iv = sg[bb * UU + 0 * 128 + lu];
        float fv = sg[bb * UU + 1 * 128 + lu];
        float gv = sg[bb * UU + 2 * 128 + lu];
        float ov = sg[bb * UU + 3 * 128 + lu];
        int b = b0 + bb;
        int u = u0 + lu;
        float cold = (t > 0) ? g_c[b * UU + u] : 0.f;
        float cn = sigmoidf_(fv) * cold + sigmoidf_(iv) * tanhf(gv);
        g_c[b * UU + u] = cn;
        g_hs[((size_t)b * TT + t) * UU + u] = sigmoidf_(ov) * tanhf(cn);
    }
}

// ---------------------------------------------------------------------------
// Final: y[b,t] = sigmoid(coef[t] * <h_bt, out_W> + shift[t]*sumW + out_b)
// One warp per (b,t).
// ---------------------------------------------------------------------------
__global__ void out_kernel(const float* __restrict__ outW,
                           const float* __restrict__ outb,
                           float* __restrict__ y)
{
    int warp = threadIdx.x >> 5;
    int lane = threadIdx.x & 31;
    int idx = blockIdx.x * 8 + warp;        // 0..16383
    int b = idx >> 8;                        // /256
    int t = idx & 255;
    const float* hp = g_hs + ((size_t)b * TT + t) * UU;
    float s = 0.f;
    #pragma unroll
    for (int u = lane; u < UU; u += 32) s += hp[u] * outW[u];
    #pragma unroll
    for (int off = 16; off > 0; off >>= 1) s += __shfl_down_sync(0xffffffffu, s, off);
    if (lane == 0) {
        float v = g_coef[t] * s + g_shift[t] * g_sumW + outb[0];
        y[idx] = 1.f / (1.f + expf(-v));
    }
}

// ---------------------------------------------------------------------------
extern "C" void kernel_launch(void* const* d_in, const int* in_sizes, int n_in,
                              void* d_out, int out_size)
{
    (void)in_sizes; (void)n_in; (void)out_size;
    const float* inputs = (const float*)d_in[0];
    const float* kernel = (const float*)d_in[1];
    const float* rec    = (const float*)d_in[2];
    const float* bias   = (const float*)d_in[3];
    const float* attW   = (const float*)d_in[4];
    const float* attb   = (const float*)d_in[5];
    const float* outW   = (const float*)d_in[6];
    const float* outb   = (const float*)d_in[7];
    float* y = (float*)d_out;

    prep_kernel<<<1, 256>>>(attW, attb, outW);
    for (int t = 0; t < TT; ++t)
        lstm_step_kernel<<<64, 128>>>(inputs, kernel, rec, bias, t);
    out_kernel<<<2048, 256>>>(outW, outb, y);
}

// round 2
// speedup vs baseline: 2.0120x; 2.0120x over previous
#include <cuda_runtime.h>
#include <math.h>

#define BB 64
#define TT 256
#define FF 64
#define UU 512
#define GG 2048      // 4*UU
#define NBLK 128
#define NTHR 256
#define CU 4         // units per block
#define NC 16        // gate-columns per block (4 gates x 4 units)
#define KT 128       // k-chunk for h staging

// ---- static device scratch (no cudaMalloc anywhere) ----
__device__ float g_hT[2][UU * BB];           // ping-pong transposed h: [u*64 + b]
__device__ float g_hsT[(size_t)TT * UU * BB]; // all h, transposed: [(t*512+u)*64 + b]
__device__ float g_coef[TT];
__device__ float g_shift[TT];
__device__ float g_sumW;
__device__ unsigned g_cnt = 0;
__device__ volatile unsigned g_gen = 0;       // monotonic across launches (never reset)

__device__ __forceinline__ float sigmoidf_(float x) { return 1.f / (1.f + expf(-x)); }

__device__ __forceinline__ void cp_async16(float* smem_dst, const void* gmem_src) {
    unsigned s = (unsigned)__cvta_generic_to_shared(smem_dst);
    asm volatile("cp.async.cg.shared.global [%0], [%1], 16;\n" :: "r"(s), "l"(gmem_src));
}
#define CP_COMMIT() asm volatile("cp.async.commit_group;\n" ::: "memory")
#define CP_WAIT1()  asm volatile("cp.async.wait_group 1;\n" ::: "memory")
#define CP_WAIT0()  asm volatile("cp.async.wait_group 0;\n" ::: "memory")

__device__ __forceinline__ void grid_barrier() {
    __threadfence();
    __syncthreads();
    if (threadIdx.x == 0) {
        unsigned gen = g_gen;
        if (atomicAdd(&g_cnt, 1u) == (unsigned)(NBLK - 1)) {
            g_cnt = 0u;
            __threadfence();
            g_gen = gen + 1u;           // release new generation
        } else {
            while (g_gen == gen) { }    // spin (volatile)
        }
    }
    __syncthreads();
}

// ---------------------------------------------------------------------------
// prep: coef[t] = (t==0)?1:sum_{j<t} att_W[t,j];  shift[t]=(t==0)?0:att_b[t];
//       sumW = sum(out_W)
// ---------------------------------------------------------------------------
__global__ void prep_kernel(const float* __restrict__ attW,
                            const float* __restrict__ attb,
                            const float* __restrict__ outW)
{
    int t = threadIdx.x;
    float s = 0.f;
    for (int j = 0; j < t; ++j) s += attW[t * TT + j];
    g_coef[t]  = (t == 0) ? 1.f : s;
    g_shift[t] = (t == 0) ? 0.f : attb[t];

    __shared__ float red[256];
    red[t] = outW[t] + outW[t + 256];
    __syncthreads();
    for (int off = 128; off > 0; off >>= 1) {
        if (t < off) red[t] += red[t + off];
        __syncthreads();
    }
    if (t == 0) g_sumW = red[0];
}

// ---------------------------------------------------------------------------
// Persistent LSTM. 128 blocks (1/SM), 256 threads.
// Block b owns units [4b, 4b+4) => 16 gate-columns, weights resident in smem.
// Per step: all-blocks read full h_prev (cp.async.cg, L2-only, double-buffered
// k-chunks), compute 64x16 gate tile, pointwise in-block (c in registers),
// write h to ping-pong g_hT + archive g_hsT, grid barrier.
// ---------------------------------------------------------------------------
// smem layout (floats):
//   sh   [2][KT*64]      = 16384
//   sW2  [16][516]       =  8256   (rec weights, [c][k] padded)
//   sWx2 [16][68]        =  1088   (input weights, [c][f] padded)
//   sx2  [64][64]        =  4096   (x_t transposed [f][b])
//   sg   [64][17]        =  1088   (gate exchange, padded)
#define OFF_SH   0
#define OFF_SW   (2 * KT * BB)
#define OFF_SWX  (OFF_SW + NC * 516)
#define OFF_SX   (OFF_SWX + NC * 68)
#define OFF_SG   (OFF_SX + FF * BB)
#define SMEM_FLOATS (OFF_SG + BB * 17)

__global__ void __launch_bounds__(NTHR, 1)
lstm_persist(const float* __restrict__ x,     // (B,T,F)
             const float* __restrict__ Wk,    // (F,4U)
             const float* __restrict__ Rk,    // (U,4U)
             const float* __restrict__ bias)  // (4U)
{
    extern __shared__ float smem[];
    float* sh   = smem + OFF_SH;
    float* sW2  = smem + OFF_SW;
    float* sWx2 = smem + OFF_SWX;
    float* sx2  = smem + OFF_SX;
    float* sg   = smem + OFF_SG;

    const int tid = threadIdx.x;
    const int bid = blockIdx.x;
    const int u0  = bid * CU;

    // ---- one-time weight staging ----
    for (int idx = tid; idx < UU * NC; idx += NTHR) {
        int k = idx >> 4, c = idx & 15;
        int gcol = (c >> 2) * UU + u0 + (c & 3);
        sW2[c * 516 + k] = Rk[(size_t)k * GG + gcol];
    }
    for (int idx = tid; idx < FF * NC; idx += NTHR) {
        int f = idx >> 4, c = idx & 15;
        int gcol = (c >> 2) * UU + u0 + (c & 3);
        sWx2[c * 68 + f] = Wk[(size_t)f * GG + gcol];
    }

    // GEMM-phase identity: thread = (batch-group, column)
    const int bg = tid >> 4;            // 0..15  -> 4 batches
    const int c  = tid & 15;            // 0..15  gate-column
    const int b0 = bg * 4;
    const int gcol = (c >> 2) * UU + u0 + (c & 3);
    const float bv = bias[gcol];

    // Pointwise-phase identity: thread = (unit, batch); c-state in register
    const int pj = tid >> 6;            // 0..3   local unit
    const int pb = tid & 63;            // 0..63  batch
    float creg = 0.f;

    __syncthreads();

    for (int t = 0; t < TT; ++t) {
        // ---- stage x_t transposed: sx2[f*64 + b] ----
        for (int i = tid; i < (BB * FF) / 4; i += NTHR) {  // 4 iters/thread
            int b  = i & 63;
            int f0 = (i >> 6) << 2;
            float4 xv = *(const float4*)(x + ((size_t)b * TT + t) * FF + f0);
            sx2[(f0 + 0) * 64 + b] = xv.x;
            sx2[(f0 + 1) * 64 + b] = xv.y;
            sx2[(f0 + 2) * 64 + b] = xv.z;
            sx2[(f0 + 3) * 64 + b] = xv.w;
        }
        __syncthreads();

        float a0 = bv, a1 = bv, a2 = bv, a3 = bv;

        // ---- input projection (K=64) ----
        #pragma unroll 4
        for (int f4 = 0; f4 < FF; f4 += 4) {
            float4 wv = *(const float4*)(sWx2 + c * 68 + f4);
            float4 x0 = *(const float4*)(sx2 + (f4 + 0) * 64 + b0);
            float4 x1 = *(const float4*)(sx2 + (f4 + 1) * 64 + b0);
            float4 x2 = *(const float4*)(sx2 + (f4 + 2) * 64 + b0);
            float4 x3 = *(const float4*)(sx2 + (f4 + 3) * 64 + b0);
            a0 += x0.x*wv.x; a1 += x0.y*wv.x; a2 += x0.z*wv.x; a3 += x0.w*wv.x;
            a0 += x1.x*wv.y; a1 += x1.y*wv.y; a2 += x1.z*wv.y; a3 += x1.w*wv.y;
            a0 += x2.x*wv.z; a1 += x2.y*wv.z; a2 += x2.z*wv.z; a3 += x2.w*wv.z;
            a0 += x3.x*wv.w; a1 += x3.y*wv.w; a2 += x3.z*wv.w; a3 += x3.w*wv.w;
        }

        // ---- recurrent projection (K=512), chunked + double-buffered ----
        if (t > 0) {
            const float* hsrc = g_hT[(t + 1) & 1];  // read buffer
            // prefetch chunk 0
            {
                const float4* src = (const float4*)hsrc;
                for (int i = tid; i < (KT * BB) / 4; i += NTHR)
                    cp_async16(sh + i * 4, src + i);
                CP_COMMIT();
            }
            #pragma unroll
            for (int ch = 0; ch < UU / KT; ++ch) {
                if (ch + 1 < UU / KT) {
                    float* dst = sh + ((ch + 1) & 1) * KT * BB;
                    const float4* src = (const float4*)(hsrc + (ch + 1) * KT * BB);
                    for (int i = tid; i < (KT * BB) / 4; i += NTHR)
                        cp_async16(dst + i * 4, src + i);
                    CP_COMMIT();
                    CP_WAIT1();
                } else {
                    CP_WAIT0();
                }
                __syncthreads();   // chunk ch visible to all

                const float* hb = sh + (ch & 1) * KT * BB;
                const float* wc = sW2 + c * 516 + ch * KT;
                #pragma unroll 4
                for (int k4 = 0; k4 < KT; k4 += 4) {
                    float4 wv = *(const float4*)(wc + k4);
                    float4 h0 = *(const float4*)(hb + (k4 + 0) * 64 + b0);
                    float4 h1 = *(const float4*)(hb + (k4 + 1) * 64 + b0);
                    float4 h2 = *(const float4*)(hb + (k4 + 2) * 64 + b0);
                    float4 h3 = *(const float4*)(hb + (k4 + 3) * 64 + b0);
                    a0 += h0.x*wv.x; a1 += h0.y*wv.x; a2 += h0.z*wv.x; a3 += h0.w*wv.x;
                    a0 += h1.x*wv.y; a1 += h1.y*wv.y; a2 += h1.z*wv.y; a3 += h1.w*wv.y;
                    a0 += h2.x*wv.z; a1 += h2.y*wv.z; a2 += h2.z*wv.z; a3 += h2.w*wv.z;
                    a0 += h3.x*wv.w; a1 += h3.y*wv.w; a2 += h3.z*wv.w; a3 += h3.w*wv.w;
                }
                __syncthreads();   // buffer free for prefetch reuse
            }
        }

        // ---- exchange gates via smem ----
        sg[(b0 + 0) * 17 + c] = a0;
        sg[(b0 + 1) * 17 + c] = a1;
        sg[(b0 + 2) * 17 + c] = a2;
        sg[(b0 + 3) * 17 + c] = a3;
        __syncthreads();

        // ---- pointwise: thread owns (unit pj, batch pb) ----
        {
            float iv = sg[pb * 17 + 0 + pj];
            float fv = sg[pb * 17 + 4 + pj];
            float gv = sg[pb * 17 + 8 + pj];
            float ov = sg[pb * 17 + 12 + pj];
            creg = sigmoidf_(fv) * creg + sigmoidf_(iv) * tanhf(gv);
            float hval = sigmoidf_(ov) * tanhf(creg);
            g_hT[t & 1][(u0 + pj) * 64 + pb] = hval;                        // ping-pong
            g_hsT[((size_t)t * UU + u0 + pj) * 64 + pb] = hval;             // archive
        }

        grid_barrier();
    }
}

// ---------------------------------------------------------------------------
// Output: y[b,t] = sigmoid(coef[t] * <h_bt, out_W> + shift[t]*sumW + out_b)
// One block per t; 256 threads = 4 u-groups x 64 batches.
// ---------------------------------------------------------------------------
__global__ void out_kernel(const float* __restrict__ outW,
                           const float* __restrict__ outb,
                           float* __restrict__ y)
{
    int t  = blockIdx.x;
    int b  = threadIdx.x & 63;
    int ug = threadIdx.x >> 6;   // 0..3
    float s = 0.f;
    const float* base = g_hsT + (size_t)t * UU * BB;
    #pragma unroll 4
    for (int u = ug * 128; u < ug * 128 + 128; ++u)
        s += base[(size_t)u * 64 + b] * outW[u];
    __shared__ float red[4][64];
    red[ug][b] = s;
    __syncthreads();
    if (ug == 0) {
        float v = red[0][b] + red[1][b] + red[2][b] + red[3][b];
        v = g_coef[t] * v + g_shift[t] * g_sumW + outb[0];
        y[b * TT + t] = 1.f / (1.f + expf(-v));
    }
}

// ---------------------------------------------------------------------------
extern "C" void kernel_launch(void* const* d_in, const int* in_sizes, int n_in,
                              void* d_out, int out_size)
{
    (void)in_sizes; (void)n_in; (void)out_size;
    const float* inputs = (const float*)d_in[0];
    const float* kernel = (const float*)d_in[1];
    const float* rec    = (const float*)d_in[2];
    const float* bias   = (const float*)d_in[3];
    const float* attW   = (const float*)d_in[4];
    const float* attb   = (const float*)d_in[5];
    const float* outW   = (const float*)d_in[6];
    const float* outb   = (const float*)d_in[7];
    float* y = (float*)d_out;

    static int smem_set = 0;
    size_t smem_bytes = SMEM_FLOATS * sizeof(float);   // ~123.6 KB
    if (!smem_set) {
        cudaFuncSetAttribute(lstm_persist,
                             cudaFuncAttributeMaxDynamicSharedMemorySize,
                             (int)smem_bytes);
        smem_set = 1;
    }

    prep_kernel<<<1, 256>>>(attW, attb, outW);
    lstm_persist<<<NBLK, NTHR, smem_bytes>>>(inputs, kernel, rec, bias);
    out_kernel<<<TT, 256>>>(outW, outb, y);
}

// round 3
// speedup vs baseline: 3.2824x; 1.6315x over previous
#include <cuda_runtime.h>
#include <math.h>

#define BB 64
#define TT 256
#define FF 64
#define UU 512
#define GG 2048      // 4*UU
#define NBLK 128
#define NTHR 128
#define CU 4         // units per block
#define NC 16        // gate-columns per block (4 gates x 4 units)
#define KT 128       // k-chunk for h staging

// ---- static device scratch (no cudaMalloc anywhere) ----
__device__ float g_hT[2][UU * BB];            // ping-pong transposed h: [u*64 + b]
__device__ float g_hsT[(size_t)TT * UU * BB]; // all h: [(t*512+u)*64 + b]
__device__ float g_coef[TT];
__device__ float g_shift[TT];
__device__ float g_sumW;
__device__ unsigned g_cnt = 0;
__device__ volatile unsigned g_gen = 0;       // monotonic across launches

__device__ __forceinline__ float sigmoidf_(float x) { return 1.f / (1.f + expf(-x)); }

// packed fp32x2 FMA (Blackwell): d = a*b + c on two lanes of a 64-bit reg
__device__ __forceinline__ unsigned long long fma2(unsigned long long a,
                                                   unsigned long long b,
                                                   unsigned long long c) {
    unsigned long long d;
    asm("fma.rn.f32x2 %0, %1, %2, %3;" : "=l"(d) : "l"(a), "l"(b), "l"(c));
    return d;
}
__device__ __forceinline__ unsigned long long pack2(float v) {
    unsigned long long p;
    unsigned u = __float_as_uint(v);
    asm("mov.b64 %0, {%1, %1};" : "=l"(p) : "r"(u));
    return p;
}

__device__ __forceinline__ void cp_async16(float* smem_dst, const void* gmem_src) {
    unsigned s = (unsigned)__cvta_generic_to_shared(smem_dst);
    asm volatile("cp.async.cg.shared.global [%0], [%1], 16;\n" :: "r"(s), "l"(gmem_src));
}
#define CP_COMMIT() asm volatile("cp.async.commit_group;\n" ::: "memory")
#define CP_WAIT1()  asm volatile("cp.async.wait_group 1;\n" ::: "memory")
#define CP_WAIT0()  asm volatile("cp.async.wait_group 0;\n" ::: "memory")

__device__ __forceinline__ void grid_barrier() {
    __threadfence();
    __syncthreads();
    if (threadIdx.x == 0) {
        unsigned gen = g_gen;
        if (atomicAdd(&g_cnt, 1u) == (unsigned)(NBLK - 1)) {
            g_cnt = 0u;
            __threadfence();
            g_gen = gen + 1u;
        } else {
            while (g_gen == gen) { }
        }
    }
    __syncthreads();
}

// ---------------------------------------------------------------------------
// prep (parallel): block t<TT computes coef/shift; block TT reduces out_W.
// ---------------------------------------------------------------------------
__global__ void prep_kernel(const float* __restrict__ attW,
                            const float* __restrict__ attb,
                            const float* __restrict__ outW)
{
    __shared__ float red[256];
    int tid = threadIdx.x;
    if (blockIdx.x < TT) {
        int t = blockIdx.x;
        float s = 0.f;
        for (int j = tid; j < t; j += 256) s += attW[t * TT + j];
        red[tid] = s;
        __syncthreads();
        for (int off = 128; off > 0; off >>= 1) {
            if (tid < off) red[tid] += red[tid + off];
            __syncthreads();
        }
        if (tid == 0) {
            g_coef[t]  = (t == 0) ? 1.f : red[0];
            g_shift[t] = (t == 0) ? 0.f : attb[t];
        }
    } else {
        red[tid] = outW[tid] + outW[tid + 256];
        __syncthreads();
        for (int off = 128; off > 0; off >>= 1) {
            if (tid < off) red[tid] += red[tid + off];
            __syncthreads();
        }
        if (tid == 0) g_sumW = red[0];
    }
}

// ---------------------------------------------------------------------------
// Persistent LSTM. 128 blocks, 128 threads. Block owns 4 units (16 gate cols).
// GEMM thread tile: 2 cols x 4 batches, accumulators as f32x2 pairs, FFMA2.
// ---------------------------------------------------------------------------
// smem (floats):
//   sh   [2][KT*64] = 16384
//   sW   [16][516]  =  8256
//   sWx  [16][68]   =  1088
//   sx2  [64][64]   =  4096
//   sg   [16][68]   =  1088
#define OFF_SH   0
#define OFF_SW   (2 * KT * BB)
#define OFF_SWX  (OFF_SW + NC * 516)
#define OFF_SX   (OFF_SWX + NC * 68)
#define OFF_SG   (OFF_SX + FF * BB)
#define SMEM_FLOATS (OFF_SG + NC * 68)

__global__ void __launch_bounds__(NTHR, 1)
lstm_persist(const float* __restrict__ x,     // (B,T,F)
             const float* __restrict__ Wk,    // (F,4U)
             const float* __restrict__ Rk,    // (U,4U)
             const float* __restrict__ bias)  // (4U)
{
    extern __shared__ float smem[];
    float* sh  = smem + OFF_SH;
    float* sW  = smem + OFF_SW;
    float* sWx = smem + OFF_SWX;
    float* sx2 = smem + OFF_SX;
    float* sg  = smem + OFF_SG;

    const int tid = threadIdx.x;
    const int bid = blockIdx.x;
    const int u0  = bid * CU;

    // one-time weight staging (c = gate*4 + unit)
    for (int idx = tid; idx < UU * NC; idx += NTHR) {
        int k = idx >> 4, c = idx & 15;
        int gcol = (c >> 2) * UU + u0 + (c & 3);
        sW[c * 516 + k] = Rk[(size_t)k * GG + gcol];
    }
    for (int idx = tid; idx < FF * NC; idx += NTHR) {
        int f = idx >> 4, c = idx & 15;
        int gcol = (c >> 2) * UU + u0 + (c & 3);
        sWx[c * 68 + f] = Wk[(size_t)f * GG + gcol];
    }

    // GEMM identity: cols {cg, cg+8}, batches [b0, b0+4)
    const int cg = tid & 7;
    const int b0 = (tid >> 3) << 2;
    const int c0 = cg, c1 = cg + 8;
    const float bv0 = bias[(c0 >> 2) * UU + u0 + (c0 & 3)];
    const float bv1 = bias[(c1 >> 2) * UU + u0 + (c1 & 3)];
    const unsigned long long bp0 = pack2(bv0);
    const unsigned long long bp1 = pack2(bv1);

    // pointwise identity: units {pj, pj+2}, batch pb
    const int pj = tid >> 6;   // 0..1
    const int pb = tid & 63;
    float creg0 = 0.f, creg1 = 0.f;

    __syncthreads();

    for (int t = 0; t < TT; ++t) {
        // stage x_t transposed: sx2[f*64 + b]
        for (int i = tid; i < (BB * FF) / 4; i += NTHR) {
            int b  = i & 63;
            int f0 = (i >> 6) << 2;
            float4 xv = *(const float4*)(x + ((size_t)b * TT + t) * FF + f0);
            sx2[(f0 + 0) * 64 + b] = xv.x;
            sx2[(f0 + 1) * 64 + b] = xv.y;
            sx2[(f0 + 2) * 64 + b] = xv.z;
            sx2[(f0 + 3) * 64 + b] = xv.w;
        }
        __syncthreads();

        unsigned long long a00 = bp0, a01 = bp0;   // col c0, pairs (b0,b0+1),(b0+2,b0+3)
        unsigned long long a10 = bp1, a11 = bp1;   // col c1

        // ---- input projection (K=64) ----
        #pragma unroll 4
        for (int f4 = 0; f4 < FF; f4 += 4) {
            float4 w0 = *(const float4*)(sWx + c0 * 68 + f4);
            float4 w1 = *(const float4*)(sWx + c1 * 68 + f4);
            #pragma unroll
            for (int kk = 0; kk < 4; ++kk) {
                ulonglong2 hv = *(const ulonglong2*)(sx2 + (f4 + kk) * 64 + b0);
                float wk0 = (kk == 0) ? w0.x : (kk == 1) ? w0.y : (kk == 2) ? w0.z : w0.w;
                float wk1 = (kk == 0) ? w1.x : (kk == 1) ? w1.y : (kk == 2) ? w1.z : w1.w;
                unsigned long long wp0 = pack2(wk0);
                unsigned long long wp1 = pack2(wk1);
                a00 = fma2(hv.x, wp0, a00); a01 = fma2(hv.y, wp0, a01);
                a10 = fma2(hv.x, wp1, a10); a11 = fma2(hv.y, wp1, a11);
            }
        }

        // ---- recurrent projection (K=512), double-buffered chunks ----
        if (t > 0) {
            const float* hsrc = g_hT[(t + 1) & 1];
            {
                const float4* src = (const float4*)hsrc;
                for (int i = tid; i < (KT * BB) / 4; i += NTHR)
                    cp_async16(sh + i * 4, src + i);
                CP_COMMIT();
            }
            #pragma unroll
            for (int ch = 0; ch < UU / KT; ++ch) {
                if (ch + 1 < UU / KT) {
                    float* dst = sh + ((ch + 1) & 1) * KT * BB;
                    const float4* src = (const float4*)(hsrc + (ch + 1) * KT * BB);
                    for (int i = tid; i < (KT * BB) / 4; i += NTHR)
                        cp_async16(dst + i * 4, src + i);
                    CP_COMMIT();
                    CP_WAIT1();
                } else {
                    CP_WAIT0();
                }
                __syncthreads();

                const float* hb  = sh + (ch & 1) * KT * BB;
                const float* wc0 = sW + c0 * 516 + ch * KT;
                const float* wc1 = sW + c1 * 516 + ch * KT;
                #pragma unroll 2
                for (int k4 = 0; k4 < KT; k4 += 4) {
                    float4 w0 = *(const float4*)(wc0 + k4);
                    float4 w1 = *(const float4*)(wc1 + k4);
                    #pragma unroll
                    for (int kk = 0; kk < 4; ++kk) {
                        ulonglong2 hv = *(const ulonglong2*)(hb + (k4 + kk) * 64 + b0);
                        float wk0 = (kk == 0) ? w0.x : (kk == 1) ? w0.y : (kk == 2) ? w0.z : w0.w;
                        float wk1 = (kk == 0) ? w1.x : (kk == 1) ? w1.y : (kk == 2) ? w1.z : w1.w;
                        unsigned long long wp0 = pack2(wk0);
                        unsigned long long wp1 = pack2(wk1);
                        a00 = fma2(hv.x, wp0, a00); a01 = fma2(hv.y, wp0, a01);
                        a10 = fma2(hv.x, wp1, a10); a11 = fma2(hv.y, wp1, a11);
                    }
                }
                __syncthreads();
            }
        }

        // ---- exchange gates via smem: sg[c*68 + b] ----
        *(ulonglong2*)(sg + c0 * 68 + b0) = make_ulonglong2(a00, a01);
        *(ulonglong2*)(sg + c1 * 68 + b0) = make_ulonglong2(a10, a11);
        __syncthreads();

        // ---- pointwise: thread owns units {pj, pj+2} x batch pb ----
        {
            float iv = sg[(0 * 4 + pj) * 68 + pb];
            float fv = sg[(1 * 4 + pj) * 68 + pb];
            float gv = sg[(2 * 4 + pj) * 68 + pb];
            float ov = sg[(3 * 4 + pj) * 68 + pb];
            creg0 = sigmoidf_(fv) * creg0 + sigmoidf_(iv) * tanhf(gv);
            float hval = sigmoidf_(ov) * tanhf(creg0);
            g_hT[t & 1][(u0 + pj) * 64 + pb] = hval;
            g_hsT[((size_t)t * UU + u0 + pj) * 64 + pb] = hval;

            int pj2 = pj + 2;
            float iv2 = sg[(0 * 4 + pj2) * 68 + pb];
            float fv2 = sg[(1 * 4 + pj2) * 68 + pb];
            float gv2 = sg[(2 * 4 + pj2) * 68 + pb];
            float ov2 = sg[(3 * 4 + pj2) * 68 + pb];
            creg1 = sigmoidf_(fv2) * creg1 + sigmoidf_(iv2) * tanhf(gv2);
            float hval2 = sigmoidf_(ov2) * tanhf(creg1);
            g_hT[t & 1][(u0 + pj2) * 64 + pb] = hval2;
            g_hsT[((size_t)t * UU + u0 + pj2) * 64 + pb] = hval2;
        }

        grid_barrier();
    }
}

// ---------------------------------------------------------------------------
// Output: y[b,t] = sigmoid(coef[t] * <h_bt, out_W> + shift[t]*sumW + out_b)
// ---------------------------------------------------------------------------
__global__ void out_kernel(const float* __restrict__ outW,
                           const float* __restrict__ outb,
                           float* __restrict__ y)
{
    int t  = blockIdx.x;
    int b  = threadIdx.x & 63;
    int ug = threadIdx.x >> 6;   // 0..3
    float s = 0.f;
    const float* base = g_hsT + (size_t)t * UU * BB;
    #pragma unroll 4
    for (int u = ug * 128; u < ug * 128 + 128; ++u)
        s += base[(size_t)u * 64 + b] * outW[u];
    __shared__ float red[4][64];
    red[ug][b] = s;
    __syncthreads();
    if (ug == 0) {
        float v = red[0][b] + red[1][b] + red[2][b] + red[3][b];
        v = g_coef[t] * v + g_shift[t] * g_sumW + outb[0];
        y[b * TT + t] = 1.f / (1.f + expf(-v));
    }
}

// ---------------------------------------------------------------------------
extern "C" void kernel_launch(void* const* d_in, const int* in_sizes, int n_in,
                              void* d_out, int out_size)
{
    (void)in_sizes; (void)n_in; (void)out_size;
    const float* inputs = (const float*)d_in[0];
    const float* kernel = (const float*)d_in[1];
    const float* rec    = (const float*)d_in[2];
    const float* bias   = (const float*)d_in[3];
    const float* attW   = (const float*)d_in[4];
    const float* attb   = (const float*)d_in[5];
    const float* outW   = (const float*)d_in[6];
    const float* outb   = (const float*)d_in[7];
    float* y = (float*)d_out;

    static int smem_set = 0;
    size_t smem_bytes = SMEM_FLOATS * sizeof(float);
    if (!smem_set) {
        cudaFuncSetAttribute(lstm_persist,
                             cudaFuncAttributeMaxDynamicSharedMemorySize,
                             (int)smem_bytes);
        smem_set = 1;
    }

    prep_kernel<<<TT + 1, 256>>>(attW, attb, outW);
    lstm_persist<<<NBLK, NTHR, smem_bytes>>>(inputs, kernel, rec, bias);
    out_kernel<<<TT, 256>>>(outW, outb, y);
}